// round 13
// baseline (speedup 1.0000x reference)
#include <cuda_runtime.h>
#include <cuda_bf16.h>
#include <cstdint>

// Problem constants
#define Bq 4
#define Hh 8
#define Ll 512
#define Dd 512
#define HDd 64
#define ZZ (Bq * Hh)
#define LL2 ((long)Ll * Ll)

// fp32 scratch
__device__ float g_S[ZZ * Ll * Ll];
__device__ float g_A[ZZ * Ll * Ll];
__device__ float g_dinv[ZZ * Ll];

// bf16 split scratch
__device__ __align__(16) __nv_bfloat16 g_x_hi[Bq * Ll * Dd];
__device__ __align__(16) __nv_bfloat16 g_x_lo[Bq * Ll * Dd];
__device__ __align__(16) __nv_bfloat16 g_WT_hi[4 * Dd * Dd];   // WqT|WkT|WvT|WoT
__device__ __align__(16) __nv_bfloat16 g_WT_lo[4 * Dd * Dd];
__device__ __align__(16) __nv_bfloat16 g_QKV_hi[Bq * Ll * 3 * Dd];
__device__ __align__(16) __nv_bfloat16 g_QKV_lo[Bq * Ll * 3 * Dd];
__device__ __align__(16) __nv_bfloat16 g_VT_hi[ZZ * HDd * Ll];
__device__ __align__(16) __nv_bfloat16 g_VT_lo[ZZ * HDd * Ll];
__device__ __align__(16) __nv_bfloat16 g_Ah_hi[ZZ * Ll * Ll];
__device__ __align__(16) __nv_bfloat16 g_Ah_lo[ZZ * Ll * Ll];
__device__ __align__(16) __nv_bfloat16 g_ST_hi[ZZ * Ll * Ll];  // S^T, later attn
__device__ __align__(16) __nv_bfloat16 g_ST_lo[ZZ * Ll * Ll];
__device__ __align__(16) __nv_bfloat16 g_T_hi[ZZ * Ll * Ll];   // T, later O
__device__ __align__(16) __nv_bfloat16 g_T_lo[ZZ * Ll * Ll];

// ===========================================================================
// mma.sync helpers (baseline PTX — compiles at compute_103)
// ===========================================================================
__device__ __forceinline__ uint32_t smem_u32(const void* p) {
    uint32_t a;
    asm("{ .reg .u64 t; cvta.to.shared.u64 t, %1; cvt.u32.u64 %0, t; }"
        : "=r"(a) : "l"(p));
    return a;
}

__device__ __forceinline__ void ldsm_x4(uint32_t addr, uint32_t* r) {
    asm volatile("ldmatrix.sync.aligned.m8n8.x4.shared.b16 {%0,%1,%2,%3}, [%4];"
                 : "=r"(r[0]), "=r"(r[1]), "=r"(r[2]), "=r"(r[3]) : "r"(addr));
}

__device__ __forceinline__ void mma_bf16(float* c, const uint32_t* a,
                                         const uint32_t* b) {
    asm volatile(
        "mma.sync.aligned.m16n8k16.row.col.f32.bf16.bf16.f32 "
        "{%0,%1,%2,%3}, {%4,%5,%6,%7}, {%8,%9}, {%0,%1,%2,%3};"
        : "+f"(c[0]), "+f"(c[1]), "+f"(c[2]), "+f"(c[3])
        : "r"(a[0]), "r"(a[1]), "r"(a[2]), "r"(a[3]), "r"(b[0]), "r"(b[1]));
}

#define CP_ASYNC16(saddr, gptr) \
    asm volatile("cp.async.cg.shared.global [%0], [%1], 16;" \
        :: "r"(saddr), "l"(gptr) : "memory")
#define CP_COMMIT() asm volatile("cp.async.commit_group;" ::: "memory")
#define CP_WAIT1()  asm volatile("cp.async.wait_group 1;" ::: "memory")
#define CP_WAIT0()  asm volatile("cp.async.wait_group 0;" ::: "memory")

// ===========================================================================
// Generalized split-bf16 TC GEMM (NT form): per z, C[i,n] = sum_k A[i,k]*B[n,k]
// A = Ahi+Alo, B = Bhi+Blo. Template AM: 2 -> N-tile 128, 1 -> N-tile 64.
// CTA M-tile 128. K multiple of 32. cp.async double-buffered.
// mode 0: write bf16 hi/lo split of C.  mode 1: write fp32 C*scale.
// ===========================================================================
#define PADR 40   // smem row stride in bf16 (80 B skew, conflict-free ldmatrix)

template <int AM>
__global__ __launch_bounds__(256, 2) void tc_gemm_g(
    const __nv_bfloat16* __restrict__ Ahi, const __nv_bfloat16* __restrict__ Alo,
    int lda, long sAb, long sAh,
    const __nv_bfloat16* __restrict__ Bhi, const __nv_bfloat16* __restrict__ Blo,
    int ldb, long sBb, long sBh,
    __nv_bfloat16* __restrict__ Ohi, __nv_bfloat16* __restrict__ Olo,
    float* __restrict__ Of32, int ldo, long sOb, long sOh,
    int K, int Hn, float scale, int mode)
{
    constexpr int NT  = (AM == 2) ? 128 : 64;
    constexpr int ASZ = 128 * PADR;      // elems per A tile (hi or lo)
    constexpr int BSZ = NT * PADR;
    constexpr int STG = 2 * (ASZ + BSZ); // elems per stage
    extern __shared__ __nv_bfloat16 smem[];

    int z = blockIdx.z, zb = z / Hn, zh = z % Hn;
    Ahi += zb * sAb + zh * sAh;  Alo += zb * sAb + zh * sAh;
    Bhi += zb * sBb + zh * sBh;  Blo += zb * sBb + zh * sBh;
    long ob = zb * sOb + zh * sOh;

    int row0 = blockIdx.y * 128, col0 = blockIdx.x * NT;
    int tid = threadIdx.x, lane = tid & 31, wid = tid >> 5;
    int wm = (AM == 2) ? (wid & 3) : wid;
    int wn = (AM == 2) ? (wid >> 2) : 0;

    uint32_t sbase = smem_u32(smem);

    float acc[AM][8][4];
#pragma unroll
    for (int i = 0; i < AM; i++)
#pragma unroll
        for (int j = 0; j < 8; j++)
#pragma unroll
            for (int k = 0; k < 4; k++) acc[i][j][k] = 0.0f;

    // ldmatrix lane addressing (constant across chunks)
    int a_r = (lane & 15);
    int a_c = ((lane >> 4) << 3);
    int b_r = ((lane >> 4) << 3) + (lane & 7);
    int b_c = (((lane >> 3) & 1) << 3);

    auto load_chunk = [&](int c, int st) {
        int k0 = c * 32;
        uint32_t sb = sbase + (uint32_t)st * STG * 2;
#pragma unroll
        for (int t = 0; t < 2; t++) {
            int idx = tid + t * 256;
            int r = idx >> 2, v = idx & 3;
            long go = (long)(row0 + r) * lda + k0 + v * 8;
            uint32_t so = (uint32_t)(r * PADR + v * 8) * 2;
            CP_ASYNC16(sb + so, Ahi + go);
            CP_ASYNC16(sb + ASZ * 2 + so, Alo + go);
        }
#pragma unroll
        for (int t = 0; t < NT / 64; t++) {
            int idx = tid + t * 256;
            int r = idx >> 2, v = idx & 3;
            long go = (long)(col0 + r) * ldb + k0 + v * 8;
            uint32_t so = (uint32_t)(r * PADR + v * 8) * 2;
            CP_ASYNC16(sb + 2 * ASZ * 2 + so, Bhi + go);
            CP_ASYNC16(sb + (2 * ASZ + BSZ) * 2 + so, Blo + go);
        }
        CP_COMMIT();
    };

    int NCH = K / 32;
    load_chunk(0, 0);
    for (int c = 0; c < NCH; c++) {
        int st = c & 1;
        if (c + 1 < NCH) { load_chunk(c + 1, st ^ 1); CP_WAIT1(); }
        else             { CP_WAIT0(); }
        __syncthreads();

        uint32_t sb  = sbase + (uint32_t)st * STG * 2;
        uint32_t aHb = sb, aLb = sb + ASZ * 2;
        uint32_t bHb = sb + 2 * ASZ * 2, bLb = sb + (2 * ASZ + BSZ) * 2;
#pragma unroll
        for (int ks = 0; ks < 2; ks++) {
            int kb = ks * 16;
            uint32_t aH[AM][4], aL[AM][4];
#pragma unroll
            for (int am = 0; am < AM; am++) {
                uint32_t off =
                    (uint32_t)((wm * (16 * AM) + am * 16 + a_r) * PADR + kb + a_c) * 2;
                ldsm_x4(aHb + off, aH[am]);
                ldsm_x4(aLb + off, aL[am]);
            }
#pragma unroll
            for (int bp = 0; bp < 4; bp++) {
                uint32_t boff =
                    (uint32_t)((wn * 64 + bp * 16 + b_r) * PADR + kb + b_c) * 2;
                uint32_t bH[4], bL[4];
                ldsm_x4(bHb + boff, bH);
                ldsm_x4(bLb + boff, bL);
#pragma unroll
                for (int am = 0; am < AM; am++)
#pragma unroll
                    for (int bna = 0; bna < 2; bna++) {
                        float* cc = acc[am][bp * 2 + bna];
                        mma_bf16(cc, aH[am], bH + bna * 2);
                        mma_bf16(cc, aH[am], bL + bna * 2);
                        mma_bf16(cc, aL[am], bH + bna * 2);
                    }
            }
        }
        __syncthreads();
    }

    // Epilogue. C fragment: c0=(r,c), c1=(r,c+1), c2=(r+8,c), c3=(r+8,c+1)
    int r_base = row0 + wm * (16 * AM) + (lane >> 2);
    int c_base = col0 + wn * 64 + 2 * (lane & 3);
#pragma unroll
    for (int am = 0; am < AM; am++)
#pragma unroll
        for (int bn = 0; bn < 8; bn++) {
            int r = r_base + am * 16;
            int c = c_base + bn * 8;
            const float* a = acc[am][bn];
            if (mode == 0) {
#pragma unroll
                for (int hrow = 0; hrow < 2; hrow++) {
                    float f0 = a[hrow * 2], f1 = a[hrow * 2 + 1];
                    __nv_bfloat16 h0 = __float2bfloat16(f0);
                    __nv_bfloat16 h1 = __float2bfloat16(f1);
                    __nv_bfloat16 l0 = __float2bfloat16(f0 - __bfloat162float(h0));
                    __nv_bfloat16 l1 = __float2bfloat16(f1 - __bfloat162float(h1));
                    long o = ob + (long)(r + hrow * 8) * ldo + c;
                    *(__nv_bfloat162*)(Ohi + o) = __halves2bfloat162(h0, h1);
                    *(__nv_bfloat162*)(Olo + o) = __halves2bfloat162(l0, l1);
                }
            } else {
#pragma unroll
                for (int hrow = 0; hrow < 2; hrow++) {
                    long o = ob + (long)(r + hrow * 8) * ldo + c;
                    float2 f2;
                    f2.x = a[hrow * 2] * scale;
                    f2.y = a[hrow * 2 + 1] * scale;
                    *(float2*)(Of32 + o) = f2;
                }
            }
        }
}

// ===========================================================================
// Elementwise / conversion kernels
// ===========================================================================
__global__ __launch_bounds__(256) void split_kernel(
    const float* __restrict__ in, __nv_bfloat16* __restrict__ hi,
    __nv_bfloat16* __restrict__ lo, int n4)
{
    int i = blockIdx.x * 256 + threadIdx.x;
    if (i >= n4) return;
    float4 v = ((const float4*)in)[i];
    float f[4] = { v.x, v.y, v.z, v.w };
    __nv_bfloat16 h[4], l[4];
#pragma unroll
    for (int j = 0; j < 4; j++) {
        h[j] = __float2bfloat16(f[j]);
        l[j] = __float2bfloat16(f[j] - __bfloat162float(h[j]));
    }
    ((__nv_bfloat162*)hi)[2 * i]     = __halves2bfloat162(h[0], h[1]);
    ((__nv_bfloat162*)hi)[2 * i + 1] = __halves2bfloat162(h[2], h[3]);
    ((__nv_bfloat162*)lo)[2 * i]     = __halves2bfloat162(l[0], l[1]);
    ((__nv_bfloat162*)lo)[2 * i + 1] = __halves2bfloat162(l[2], l[3]);
}

// Batched W transpose+split: mat m (blockIdx.z) of {W0,W1,W2}; out offset m*512*512.
// out[m][c][r] = split(Wm[r][c])
__global__ __launch_bounds__(256) void wsplit_kernel(
    const float* __restrict__ W0, const float* __restrict__ W1,
    const float* __restrict__ W2,
    __nv_bfloat16* __restrict__ hi, __nv_bfloat16* __restrict__ lo)
{
    __shared__ float t[32][33];
    int m = blockIdx.z;
    const float* W = (m == 0) ? W0 : ((m == 1) ? W1 : W2);
    long zo = (long)m * LL2;   // 512*512 per matrix
    int c0 = blockIdx.x * 32, r0 = blockIdx.y * 32;
    int tx = threadIdx.x & 31, ty = threadIdx.x >> 5;
#pragma unroll
    for (int i = 0; i < 4; i++)
        t[ty + i * 8][tx] = W[(long)(r0 + ty + i * 8) * Dd + c0 + tx];
    __syncthreads();
#pragma unroll
    for (int i = 0; i < 4; i++) {
        float v = t[tx][ty + i * 8];
        __nv_bfloat16 h = __float2bfloat16(v);
        __nv_bfloat16 l = __float2bfloat16(v - __bfloat162float(h));
        long o = zo + (long)(c0 + ty + i * 8) * Dd + r0 + tx;
        hi[o] = h;
        lo[o] = l;
    }
}

// transpose + split: out[z][c][r] = split(in[z][r][c]); 512x512 per z
__global__ __launch_bounds__(256) void split_trans_kernel(
    const float* __restrict__ S, __nv_bfloat16* __restrict__ hi,
    __nv_bfloat16* __restrict__ lo)
{
    __shared__ float t[32][33];
    int z = blockIdx.z;
    long zo = (long)z * LL2;
    int c0 = blockIdx.x * 32, r0 = blockIdx.y * 32;
    int tx = threadIdx.x & 31, ty = threadIdx.x >> 5;
#pragma unroll
    for (int i = 0; i < 4; i++)
        t[ty + i * 8][tx] = S[zo + (long)(r0 + ty + i * 8) * Ll + c0 + tx];
    __syncthreads();
#pragma unroll
    for (int i = 0; i < 4; i++) {
        float v = t[tx][ty + i * 8];
        __nv_bfloat16 h = __float2bfloat16(v);
        __nv_bfloat16 l = __float2bfloat16(v - __bfloat162float(h));
        long o = zo + (long)(c0 + ty + i * 8) * Ll + r0 + tx;
        hi[o] = h;
        lo[o] = l;
    }
}

// V^T extraction (bf16 -> bf16): VT[z][d][j] = QKV[(b*512+j)*1536 + 1024 + h*64 + d]
__global__ __launch_bounds__(256) void vt_transpose(
    const __nv_bfloat16* __restrict__ Qh, const __nv_bfloat16* __restrict__ Ql,
    __nv_bfloat16* __restrict__ VTh, __nv_bfloat16* __restrict__ VTl)
{
    __shared__ __nv_bfloat16 th[32][72], tl[32][72];
    int z = blockIdx.z, b = z >> 3, h = z & 7;
    int j0 = blockIdx.x * 32;
    int t = threadIdx.x;
    int r = t >> 3, v = t & 7;
    long src = (long)(b * 512 + j0 + r) * 1536 + 1024 + h * 64 + v * 8;
    *(uint4*)&th[r][v * 8] = *(const uint4*)(Qh + src);
    *(uint4*)&tl[r][v * 8] = *(const uint4*)(Ql + src);
    __syncthreads();
    long zo = (long)z * HDd * Ll;
#pragma unroll
    for (int i = 0; i < 8; i++) {
        int e = t + i * 256;
        int d = e >> 5, j = e & 31;
        VTh[zo + (long)d * Ll + j0 + j] = th[j][d];
        VTl[zo + (long)d * Ll + j0 + j] = tl[j][d];
    }
}

// Fused A_hat + split (fp32 A_hat never materialized)
__global__ __launch_bounds__(256) void ahat_split_kernel(
    const float* __restrict__ A, const float* __restrict__ dinv,
    __nv_bfloat16* __restrict__ hi, __nv_bfloat16* __restrict__ lo)
{
    long n4 = (long)ZZ * Ll * Ll / 4;
    for (long i = (long)blockIdx.x * blockDim.x + threadIdx.x; i < n4;
         i += (long)gridDim.x * blockDim.x) {
        long x = i * 4;
        long z = x >> 18;
        int r = (int)((x >> 9) & 511);
        int c = (int)(x & 511);
        float dr = dinv[z * Ll + r];
        const float* dc = dinv + z * Ll + c;
        float4 v = ((const float4*)A)[i];
        float f[4] = { v.x, v.y, v.z, v.w };
#pragma unroll
        for (int j = 0; j < 4; j++) {
            float a = f[j] + ((c + j) == r ? 1.0f : 0.0f);
            f[j] = a * dr * dc[j];
        }
        __nv_bfloat16 h[4], l[4];
#pragma unroll
        for (int j = 0; j < 4; j++) {
            h[j] = __float2bfloat16(f[j]);
            l[j] = __float2bfloat16(f[j] - __bfloat162float(h[j]));
        }
        ((__nv_bfloat162*)hi)[2 * i]     = __halves2bfloat162(h[0], h[1]);
        ((__nv_bfloat162*)hi)[2 * i + 1] = __halves2bfloat162(h[2], h[3]);
        ((__nv_bfloat162*)lo)[2 * i]     = __halves2bfloat162(l[0], l[1]);
        ((__nv_bfloat162*)lo)[2 * i + 1] = __halves2bfloat162(l[2], l[3]);
    }
}

// ===========================================================================
// Adjacency (fp32 SIMT, symmetric tile pairs). j-tile 64, float4 loads.
// A[i,k] = 1/(L*HD) * sum_j S[i,j]*S[k,j] * [S[i,j]*S[k,j] > RHO*HD], diag 0.
// ===========================================================================
__global__ __launch_bounds__(256) void adj_kernel(const float* __restrict__ S,
                                                  float* __restrict__ A)
{
    int z = blockIdx.z;
    const float* Sh = S + (long)z * Ll * Ll;
    float* Ah = A + (long)z * Ll * Ll;

    int rem = blockIdx.x;
    int ti = 0;
    while (rem >= (8 - ti)) { rem -= (8 - ti); ti++; }
    int tk = ti + rem;
    int i0 = ti * 64, k0 = tk * 64;

    __shared__ float Si[64][68];
    __shared__ float Sk[64][68];

    int tid = threadIdx.x;
    int tx = tid & 15, ty = tid >> 4;
    const float THR = 0.1f * 64.0f;

    // load mapping: row li (0..63), j-window jb..jb+15 (4 float4s)
    int li = tid >> 2, jb = (tid & 3) * 16;

    float acc[4][4] = {};

    for (int j0 = 0; j0 < Ll; j0 += 64) {
        __syncthreads();   // prior iter's readers done before overwrite
#pragma unroll
        for (int v = 0; v < 4; v++) {
            float4 f = *(const float4*)&Sh[(long)(i0 + li) * Ll + j0 + jb + v * 4];
            Si[jb + v * 4 + 0][li] = f.x;
            Si[jb + v * 4 + 1][li] = f.y;
            Si[jb + v * 4 + 2][li] = f.z;
            Si[jb + v * 4 + 3][li] = f.w;
            float4 g = *(const float4*)&Sh[(long)(k0 + li) * Ll + j0 + jb + v * 4];
            Sk[jb + v * 4 + 0][li] = g.x;
            Sk[jb + v * 4 + 1][li] = g.y;
            Sk[jb + v * 4 + 2][li] = g.z;
            Sk[jb + v * 4 + 3][li] = g.w;
        }
        __syncthreads();
#pragma unroll 16
        for (int j = 0; j < 64; j++) {
            float4 av = *(const float4*)&Si[j][ty * 4];
            float4 bv = *(const float4*)&Sk[j][tx * 4];
            float a[4] = {av.x, av.y, av.z, av.w};
            float b[4] = {bv.x, bv.y, bv.z, bv.w};
#pragma unroll
            for (int ii = 0; ii < 4; ii++)
#pragma unroll
                for (int kk = 0; kk < 4; kk++) {
                    float t = a[ii] * b[kk];
                    if (t > THR) acc[ii][kk] += t;
                }
        }
    }

    const float inv = 1.0f / (64.0f * 512.0f);
#pragma unroll
    for (int ii = 0; ii < 4; ii++)
#pragma unroll
        for (int kk = 0; kk < 4; kk++) {
            int gi = i0 + ty * 4 + ii, gk = k0 + tx * 4 + kk;
            float v = (gi == gk) ? 0.0f : acc[ii][kk] * inv;
            Ah[(long)gi * Ll + gk] = v;
            if (ti != tk) Ah[(long)gk * Ll + gi] = v;
        }
}

__global__ __launch_bounds__(256) void rowsum_kernel(const float* __restrict__ A,
                                                     float* __restrict__ dinv)
{
    long row = blockIdx.x;
    const float* a = A + row * Ll;
    int t = threadIdx.x;
    float s = a[t] + a[t + 256];
#pragma unroll
    for (int o = 16; o > 0; o >>= 1) s += __shfl_xor_sync(0xFFFFFFFFu, s, o);
    __shared__ float red[8];
    if ((t & 31) == 0) red[t >> 5] = s;
    __syncthreads();
    if (t == 0) {
        float tot = 1.0f;
        for (int w = 0; w < 8; w++) tot += red[w];
        tot = fmaxf(tot, 1e-6f);
        dinv[row] = rsqrtf(tot);
    }
}

// softmax fused with bf16 hi/lo split of the attn weights
__global__ __launch_bounds__(256) void softmax_split(
    const float* __restrict__ S, __nv_bfloat16* __restrict__ hi,
    __nv_bfloat16* __restrict__ lo)
{
    long row = blockIdx.x;
    const float* s = S + row * Ll;
    int t = threadIdx.x;
    float v0 = s[t], v1 = s[t + 256];

    __shared__ float red[8];
    float m = fmaxf(v0, v1);
#pragma unroll
    for (int o = 16; o > 0; o >>= 1) m = fmaxf(m, __shfl_xor_sync(0xFFFFFFFFu, m, o));
    if ((t & 31) == 0) red[t >> 5] = m;
    __syncthreads();
    float mm = red[0];
#pragma unroll
    for (int w = 1; w < 8; w++) mm = fmaxf(mm, red[w]);
    __syncthreads();

    float e0 = expf(v0 - mm), e1 = expf(v1 - mm);
    float ssum = e0 + e1;
#pragma unroll
    for (int o = 16; o > 0; o >>= 1) ssum += __shfl_xor_sync(0xFFFFFFFFu, ssum, o);
    if ((t & 31) == 0) red[t >> 5] = ssum;
    __syncthreads();
    float tot = 0.0f;
#pragma unroll
    for (int w = 0; w < 8; w++) tot += red[w];
    float inv = 1.0f / tot;
    float p0 = e0 * inv, p1 = e1 * inv;
    __nv_bfloat16 h0 = __float2bfloat16(p0);
    __nv_bfloat16 h1 = __float2bfloat16(p1);
    hi[row * Ll + t]       = h0;
    hi[row * Ll + t + 256] = h1;
    lo[row * Ll + t]       = __float2bfloat16(p0 - __bfloat162float(h0));
    lo[row * Ll + t + 256] = __float2bfloat16(p1 - __bfloat162float(h1));
}

// ===========================================================================
extern "C" void kernel_launch(void* const* d_in, const int* in_sizes, int n_in,
                              void* d_out, int out_size)
{
    const float* x  = (const float*)d_in[0];
    const float* Wq = (const float*)d_in[1];
    const float* Wk = (const float*)d_in[2];
    const float* Wv = (const float*)d_in[3];
    const float* Wo = (const float*)d_in[4];
    float* out = (float*)d_out;

    float *Sp, *Ap, *Dp;
    cudaGetSymbolAddress((void**)&Sp, g_S);
    cudaGetSymbolAddress((void**)&Ap, g_A);
    cudaGetSymbolAddress((void**)&Dp, g_dinv);

    __nv_bfloat16 *xH, *xL, *WTH, *WTL, *QKH, *QKL, *VTH, *VTL;
    __nv_bfloat16 *AhH, *AhL, *STH, *STL, *TH, *TL;
    cudaGetSymbolAddress((void**)&xH, g_x_hi);
    cudaGetSymbolAddress((void**)&xL, g_x_lo);
    cudaGetSymbolAddress((void**)&WTH, g_WT_hi);
    cudaGetSymbolAddress((void**)&WTL, g_WT_lo);
    cudaGetSymbolAddress((void**)&QKH, g_QKV_hi);
    cudaGetSymbolAddress((void**)&QKL, g_QKV_lo);
    cudaGetSymbolAddress((void**)&VTH, g_VT_hi);
    cudaGetSymbolAddress((void**)&VTL, g_VT_lo);
    cudaGetSymbolAddress((void**)&AhH, g_Ah_hi);
    cudaGetSymbolAddress((void**)&AhL, g_Ah_lo);
    cudaGetSymbolAddress((void**)&STH, g_ST_hi);
    cudaGetSymbolAddress((void**)&STL, g_ST_lo);
    cudaGetSymbolAddress((void**)&TH, g_T_hi);
    cudaGetSymbolAddress((void**)&TL, g_T_lo);

    // dynamic smem sizes: AM=2: 81920B; AM=1: 61440B
    const int SM2 = 2 * (2 * 128 * PADR + 2 * 128 * PADR) * 2;
    const int SM1 = 2 * (2 * 128 * PADR + 2 * 64 * PADR) * 2;
    cudaFuncSetAttribute(tc_gemm_g<2>, cudaFuncAttributeMaxDynamicSharedMemorySize, SM2);
    cudaFuncSetAttribute(tc_gemm_g<1>, cudaFuncAttributeMaxDynamicSharedMemorySize, SM1);

    // Launch order arranged so adj_kernel is the 6th launch (ncu -s 5 -c 1
    // captures it next round).
    // 1) x split
    split_kernel<<<1024, 256>>>(x, xH, xL, Bq * Ll * Dd / 4);
    // 2) Wq|Wk|Wv transpose+split (batched over grid.z)
    wsplit_kernel<<<dim3(16, 16, 3), 256>>>(Wq, Wk, Wv, WTH, WTL);
    // 3) Wo transpose+split
    wsplit_kernel<<<dim3(16, 16, 1), 256>>>(Wo, Wo, Wo,
                                            WTH + 3L * 512 * 512, WTL + 3L * 512 * 512);

    // 4) QKV = x @ [Wq|Wk|Wv]  -> bf16 hi/lo [2048 x 1536]
    tc_gemm_g<2><<<dim3(12, 16, 1), 256, SM2>>>(
        xH, xL, Dd, 0, 0,
        WTH, WTL, Dd, 0, 0,
        QKH, QKL, nullptr, 3 * Dd, 0, 0,
        Dd, 1, 1.0f, 0);

    // 5) S = Q @ K^T per head -> fp32 g_S
    tc_gemm_g<2><<<dim3(4, 4, ZZ), 256, SM2>>>(
        QKH, QKL, 3 * Dd, (long)Ll * 3 * Dd, HDd,
        QKH + Dd, QKL + Dd, 3 * Dd, (long)Ll * 3 * Dd, HDd,
        nullptr, nullptr, Sp, Ll, (long)Hh * LL2, LL2,
        HDd, Hh, 1.0f, 1);

    // 6) adjacency  <- profiled launch
    adj_kernel<<<dim3(36, 1, ZZ), 256>>>(Sp, Ap);

    // 7) degrees
    rowsum_kernel<<<ZZ * Ll, 256>>>(Ap, Dp);

    // 8) fused A_hat + split
    ahat_split_kernel<<<4096, 256>>>(Ap, Dp, AhH, AhL);

    // 9) S^T split (B operand of jump1)
    split_trans_kernel<<<dim3(16, 16, ZZ), 256>>>(Sp, STH, STL);

    // 10) T = A_hat @ S -> bf16 hi/lo
    tc_gemm_g<2><<<dim3(4, 4, ZZ), 256, SM2>>>(
        AhH, AhL, Ll, LL2, 0,
        STH, STL, Ll, LL2, 0,
        TH, TL, nullptr, Ll, LL2, 0,
        Ll, 1, 1.0f, 0);

    // 11) S_jump = (T @ A_hat) / 8 -> fp32 g_S
    tc_gemm_g<2><<<dim3(4, 4, ZZ), 256, SM2>>>(
        TH, TL, Ll, LL2, 0,
        AhH, AhL, Ll, LL2, 0,
        nullptr, nullptr, Sp, Ll, LL2, 0,
        Ll, 1, 0.125f, 1);

    // 12) softmax + attn split (into ST buffers)
    softmax_split<<<ZZ * Ll, 256>>>(Sp, STH, STL);

    // 13) V^T extraction from QKV
    vt_transpose<<<dim3(16, 1, ZZ), 256>>>(QKH, QKL, VTH, VTL);

    // 14) O = attn @ V -> bf16 hi/lo into T buffers
    tc_gemm_g<1><<<dim3(1, 4, ZZ), 256, SM1>>>(
        STH, STL, Ll, (long)Hh * LL2, LL2,
        VTH, VTL, Ll, (long)Hh * HDd * Ll, (long)HDd * Ll,
        TH, TL, nullptr, Dd, (long)Ll * Dd, HDd,
        Ll, Hh, 1.0f, 0);

    // 15) out = O @ Wo -> fp32 d_out
    tc_gemm_g<2><<<dim3(4, 16, 1), 256, SM2>>>(
        TH, TL, Dd, 0, 0,
        WTH + 3L * 512 * 512, WTL + 3L * 512 * 512, Dd, 0, 0,
        nullptr, nullptr, out, Dd, 0, 0,
        Dd, 1, 1.0f, 1);
}

// round 17
// speedup vs baseline: 1.0572x; 1.0572x over previous
#include <cuda_runtime.h>
#include <cuda_bf16.h>
#include <cstdint>

// Problem constants
#define Bq 4
#define Hh 8
#define Ll 512
#define Dd 512
#define HDd 64
#define ZZ (Bq * Hh)
#define LL2 ((long)Ll * Ll)

// fp32 scratch
__device__ float g_S[ZZ * Ll * Ll];
__device__ float g_A[ZZ * Ll * Ll];
__device__ float g_dinv[ZZ * Ll];

// bf16 split scratch
__device__ __align__(16) __nv_bfloat16 g_x_hi[Bq * Ll * Dd];
__device__ __align__(16) __nv_bfloat16 g_x_lo[Bq * Ll * Dd];
__device__ __align__(16) __nv_bfloat16 g_WT_hi[4 * Dd * Dd];   // WqT|WkT|WvT|WoT
__device__ __align__(16) __nv_bfloat16 g_WT_lo[4 * Dd * Dd];
__device__ __align__(16) __nv_bfloat16 g_QKV_hi[Bq * Ll * 3 * Dd];
__device__ __align__(16) __nv_bfloat16 g_QKV_lo[Bq * Ll * 3 * Dd];
__device__ __align__(16) __nv_bfloat16 g_VT_hi[ZZ * HDd * Ll];
__device__ __align__(16) __nv_bfloat16 g_VT_lo[ZZ * HDd * Ll];
__device__ __align__(16) __nv_bfloat16 g_Ah_hi[ZZ * Ll * Ll];
__device__ __align__(16) __nv_bfloat16 g_Ah_lo[ZZ * Ll * Ll];
__device__ __align__(16) __nv_bfloat16 g_ST_hi[ZZ * Ll * Ll];  // S^T, later attn
__device__ __align__(16) __nv_bfloat16 g_ST_lo[ZZ * Ll * Ll];
__device__ __align__(16) __nv_bfloat16 g_T_hi[ZZ * Ll * Ll];   // T, later O
__device__ __align__(16) __nv_bfloat16 g_T_lo[ZZ * Ll * Ll];

// ===========================================================================
// mma.sync helpers (baseline PTX — compiles at compute_103)
// ===========================================================================
__device__ __forceinline__ uint32_t smem_u32(const void* p) {
    uint32_t a;
    asm("{ .reg .u64 t; cvta.to.shared.u64 t, %1; cvt.u32.u64 %0, t; }"
        : "=r"(a) : "l"(p));
    return a;
}

__device__ __forceinline__ void ldsm_x4(uint32_t addr, uint32_t* r) {
    asm volatile("ldmatrix.sync.aligned.m8n8.x4.shared.b16 {%0,%1,%2,%3}, [%4];"
                 : "=r"(r[0]), "=r"(r[1]), "=r"(r[2]), "=r"(r[3]) : "r"(addr));
}

__device__ __forceinline__ void mma_bf16(float* c, const uint32_t* a,
                                         const uint32_t* b) {
    asm volatile(
        "mma.sync.aligned.m16n8k16.row.col.f32.bf16.bf16.f32 "
        "{%0,%1,%2,%3}, {%4,%5,%6,%7}, {%8,%9}, {%0,%1,%2,%3};"
        : "+f"(c[0]), "+f"(c[1]), "+f"(c[2]), "+f"(c[3])
        : "r"(a[0]), "r"(a[1]), "r"(a[2]), "r"(a[3]), "r"(b[0]), "r"(b[1]));
}

#define CP_ASYNC16(saddr, gptr) \
    asm volatile("cp.async.cg.shared.global [%0], [%1], 16;" \
        :: "r"(saddr), "l"(gptr) : "memory")
#define CP_COMMIT() asm volatile("cp.async.commit_group;" ::: "memory")
#define CP_WAIT1()  asm volatile("cp.async.wait_group 1;" ::: "memory")
#define CP_WAIT0()  asm volatile("cp.async.wait_group 0;" ::: "memory")

// ===========================================================================
// Generalized split-bf16 TC GEMM (NT form): per z, C[i,n] = sum_k A[i,k]*B[n,k]
// A = Ahi+Alo, B = Bhi+Blo. Template AM: 2 -> N-tile 128, 1 -> N-tile 64.
// CTA M-tile 128. K multiple of 32. cp.async double-buffered.
// mode 0: write bf16 hi/lo split of C.  mode 1: write fp32 C*scale.
// ===========================================================================
#define PADR 40   // smem row stride in bf16 (80 B skew, conflict-free ldmatrix)

template <int AM>
__global__ __launch_bounds__(256, 2) void tc_gemm_g(
    const __nv_bfloat16* __restrict__ Ahi, const __nv_bfloat16* __restrict__ Alo,
    int lda, long sAb, long sAh,
    const __nv_bfloat16* __restrict__ Bhi, const __nv_bfloat16* __restrict__ Blo,
    int ldb, long sBb, long sBh,
    __nv_bfloat16* __restrict__ Ohi, __nv_bfloat16* __restrict__ Olo,
    float* __restrict__ Of32, int ldo, long sOb, long sOh,
    int K, int Hn, float scale, int mode)
{
    constexpr int NT  = (AM == 2) ? 128 : 64;
    constexpr int ASZ = 128 * PADR;      // elems per A tile (hi or lo)
    constexpr int BSZ = NT * PADR;
    constexpr int STG = 2 * (ASZ + BSZ); // elems per stage
    extern __shared__ __nv_bfloat16 smem[];

    int z = blockIdx.z, zb = z / Hn, zh = z % Hn;
    Ahi += zb * sAb + zh * sAh;  Alo += zb * sAb + zh * sAh;
    Bhi += zb * sBb + zh * sBh;  Blo += zb * sBb + zh * sBh;
    long ob = zb * sOb + zh * sOh;

    int row0 = blockIdx.y * 128, col0 = blockIdx.x * NT;
    int tid = threadIdx.x, lane = tid & 31, wid = tid >> 5;
    int wm = (AM == 2) ? (wid & 3) : wid;
    int wn = (AM == 2) ? (wid >> 2) : 0;

    uint32_t sbase = smem_u32(smem);

    float acc[AM][8][4];
#pragma unroll
    for (int i = 0; i < AM; i++)
#pragma unroll
        for (int j = 0; j < 8; j++)
#pragma unroll
            for (int k = 0; k < 4; k++) acc[i][j][k] = 0.0f;

    // ldmatrix lane addressing (constant across chunks)
    int a_r = (lane & 15);
    int a_c = ((lane >> 4) << 3);
    int b_r = ((lane >> 4) << 3) + (lane & 7);
    int b_c = (((lane >> 3) & 1) << 3);

    auto load_chunk = [&](int c, int st) {
        int k0 = c * 32;
        uint32_t sb = sbase + (uint32_t)st * STG * 2;
#pragma unroll
        for (int t = 0; t < 2; t++) {
            int idx = tid + t * 256;
            int r = idx >> 2, v = idx & 3;
            long go = (long)(row0 + r) * lda + k0 + v * 8;
            uint32_t so = (uint32_t)(r * PADR + v * 8) * 2;
            CP_ASYNC16(sb + so, Ahi + go);
            CP_ASYNC16(sb + ASZ * 2 + so, Alo + go);
        }
#pragma unroll
        for (int t = 0; t < NT / 64; t++) {
            int idx = tid + t * 256;
            int r = idx >> 2, v = idx & 3;
            long go = (long)(col0 + r) * ldb + k0 + v * 8;
            uint32_t so = (uint32_t)(r * PADR + v * 8) * 2;
            CP_ASYNC16(sb + 2 * ASZ * 2 + so, Bhi + go);
            CP_ASYNC16(sb + (2 * ASZ + BSZ) * 2 + so, Blo + go);
        }
        CP_COMMIT();
    };

    int NCH = K / 32;
    load_chunk(0, 0);
    for (int c = 0; c < NCH; c++) {
        int st = c & 1;
        if (c + 1 < NCH) { load_chunk(c + 1, st ^ 1); CP_WAIT1(); }
        else             { CP_WAIT0(); }
        __syncthreads();

        uint32_t sb  = sbase + (uint32_t)st * STG * 2;
        uint32_t aHb = sb, aLb = sb + ASZ * 2;
        uint32_t bHb = sb + 2 * ASZ * 2, bLb = sb + (2 * ASZ + BSZ) * 2;
#pragma unroll
        for (int ks = 0; ks < 2; ks++) {
            int kb = ks * 16;
            uint32_t aH[AM][4], aL[AM][4];
#pragma unroll
            for (int am = 0; am < AM; am++) {
                uint32_t off =
                    (uint32_t)((wm * (16 * AM) + am * 16 + a_r) * PADR + kb + a_c) * 2;
                ldsm_x4(aHb + off, aH[am]);
                ldsm_x4(aLb + off, aL[am]);
            }
#pragma unroll
            for (int bp = 0; bp < 4; bp++) {
                uint32_t boff =
                    (uint32_t)((wn * 64 + bp * 16 + b_r) * PADR + kb + b_c) * 2;
                uint32_t bH[4], bL[4];
                ldsm_x4(bHb + boff, bH);
                ldsm_x4(bLb + boff, bL);
#pragma unroll
                for (int am = 0; am < AM; am++)
#pragma unroll
                    for (int bna = 0; bna < 2; bna++) {
                        float* cc = acc[am][bp * 2 + bna];
                        mma_bf16(cc, aH[am], bH + bna * 2);
                        mma_bf16(cc, aH[am], bL + bna * 2);
                        mma_bf16(cc, aL[am], bH + bna * 2);
                    }
            }
        }
        __syncthreads();
    }

    // Epilogue. C fragment: c0=(r,c), c1=(r,c+1), c2=(r+8,c), c3=(r+8,c+1)
    int r_base = row0 + wm * (16 * AM) + (lane >> 2);
    int c_base = col0 + wn * 64 + 2 * (lane & 3);
#pragma unroll
    for (int am = 0; am < AM; am++)
#pragma unroll
        for (int bn = 0; bn < 8; bn++) {
            int r = r_base + am * 16;
            int c = c_base + bn * 8;
            const float* a = acc[am][bn];
            if (mode == 0) {
#pragma unroll
                for (int hrow = 0; hrow < 2; hrow++) {
                    float f0 = a[hrow * 2], f1 = a[hrow * 2 + 1];
                    __nv_bfloat16 h0 = __float2bfloat16(f0);
                    __nv_bfloat16 h1 = __float2bfloat16(f1);
                    __nv_bfloat16 l0 = __float2bfloat16(f0 - __bfloat162float(h0));
                    __nv_bfloat16 l1 = __float2bfloat16(f1 - __bfloat162float(h1));
                    long o = ob + (long)(r + hrow * 8) * ldo + c;
                    *(__nv_bfloat162*)(Ohi + o) = __halves2bfloat162(h0, h1);
                    *(__nv_bfloat162*)(Olo + o) = __halves2bfloat162(l0, l1);
                }
            } else {
#pragma unroll
                for (int hrow = 0; hrow < 2; hrow++) {
                    long o = ob + (long)(r + hrow * 8) * ldo + c;
                    float2 f2;
                    f2.x = a[hrow * 2] * scale;
                    f2.y = a[hrow * 2 + 1] * scale;
                    *(float2*)(Of32 + o) = f2;
                }
            }
        }
}

// ===========================================================================
// Combined input split: z 0..3 -> straight split of x quarter z;
// z 4..7 -> transpose+split of W[z-4] into WT block (z-4).
// ===========================================================================
__global__ __launch_bounds__(256) void combo_split(
    const float* __restrict__ x,
    const float* __restrict__ W0, const float* __restrict__ W1,
    const float* __restrict__ W2, const float* __restrict__ W3,
    __nv_bfloat16* __restrict__ xhi, __nv_bfloat16* __restrict__ xlo,
    __nv_bfloat16* __restrict__ whi, __nv_bfloat16* __restrict__ wlo)
{
    int m = blockIdx.z;
    int c0 = blockIdx.x * 32, r0 = blockIdx.y * 32;
    if (m < 4) {
        // straight split of x rows [m*512 + r0, +32), cols [c0, +32)
        int r = threadIdx.x >> 3, v = threadIdx.x & 7;
        long o = (long)(m * 512 + r0 + r) * Dd + c0 + v * 4;
        float4 f = *(const float4*)(x + o);
        float fv[4] = { f.x, f.y, f.z, f.w };
        __nv_bfloat16 h[4], l[4];
#pragma unroll
        for (int j = 0; j < 4; j++) {
            h[j] = __float2bfloat16(fv[j]);
            l[j] = __float2bfloat16(fv[j] - __bfloat162float(h[j]));
        }
        *(__nv_bfloat162*)(xhi + o)     = __halves2bfloat162(h[0], h[1]);
        *(__nv_bfloat162*)(xhi + o + 2) = __halves2bfloat162(h[2], h[3]);
        *(__nv_bfloat162*)(xlo + o)     = __halves2bfloat162(l[0], l[1]);
        *(__nv_bfloat162*)(xlo + o + 2) = __halves2bfloat162(l[2], l[3]);
    } else {
        __shared__ float t[32][33];
        const float* W = (m == 4) ? W0 : ((m == 5) ? W1 : ((m == 6) ? W2 : W3));
        long zo = (long)(m - 4) * LL2;
        int tx = threadIdx.x & 31, ty = threadIdx.x >> 5;
#pragma unroll
        for (int i = 0; i < 4; i++)
            t[ty + i * 8][tx] = W[(long)(r0 + ty + i * 8) * Dd + c0 + tx];
        __syncthreads();
#pragma unroll
        for (int i = 0; i < 4; i++) {
            float v = t[tx][ty + i * 8];
            __nv_bfloat16 h = __float2bfloat16(v);
            __nv_bfloat16 l = __float2bfloat16(v - __bfloat162float(h));
            long o = zo + (long)(c0 + ty + i * 8) * Dd + r0 + tx;
            whi[o] = h;
            wlo[o] = l;
        }
    }
}

// transpose + split: out[z][c][r] = split(in[z][r][c]); 512x512 per z
__global__ __launch_bounds__(256) void split_trans_kernel(
    const float* __restrict__ S, __nv_bfloat16* __restrict__ hi,
    __nv_bfloat16* __restrict__ lo)
{
    __shared__ float t[32][33];
    int z = blockIdx.z;
    long zo = (long)z * LL2;
    int c0 = blockIdx.x * 32, r0 = blockIdx.y * 32;
    int tx = threadIdx.x & 31, ty = threadIdx.x >> 5;
#pragma unroll
    for (int i = 0; i < 4; i++)
        t[ty + i * 8][tx] = S[zo + (long)(r0 + ty + i * 8) * Ll + c0 + tx];
    __syncthreads();
#pragma unroll
    for (int i = 0; i < 4; i++) {
        float v = t[tx][ty + i * 8];
        __nv_bfloat16 h = __float2bfloat16(v);
        __nv_bfloat16 l = __float2bfloat16(v - __bfloat162float(h));
        long o = zo + (long)(c0 + ty + i * 8) * Ll + r0 + tx;
        hi[o] = h;
        lo[o] = l;
    }
}

// V^T extraction (bf16 -> bf16): VT[z][d][j] = QKV[(b*512+j)*1536 + 1024 + h*64 + d]
__global__ __launch_bounds__(256) void vt_transpose(
    const __nv_bfloat16* __restrict__ Qh, const __nv_bfloat16* __restrict__ Ql,
    __nv_bfloat16* __restrict__ VTh, __nv_bfloat16* __restrict__ VTl)
{
    __shared__ __nv_bfloat16 th[32][72], tl[32][72];
    int z = blockIdx.z, b = z >> 3, h = z & 7;
    int j0 = blockIdx.x * 32;
    int t = threadIdx.x;
    int r = t >> 3, v = t & 7;
    long src = (long)(b * 512 + j0 + r) * 1536 + 1024 + h * 64 + v * 8;
    *(uint4*)&th[r][v * 8] = *(const uint4*)(Qh + src);
    *(uint4*)&tl[r][v * 8] = *(const uint4*)(Ql + src);
    __syncthreads();
    long zo = (long)z * HDd * Ll;
#pragma unroll
    for (int i = 0; i < 8; i++) {
        int e = t + i * 256;
        int d = e >> 5, j = e & 31;
        VTh[zo + (long)d * Ll + j0 + j] = th[j][d];
        VTl[zo + (long)d * Ll + j0 + j] = tl[j][d];
    }
}

// Fused A_hat + split (fp32 A_hat never materialized)
__global__ __launch_bounds__(256) void ahat_split_kernel(
    const float* __restrict__ A, const float* __restrict__ dinv,
    __nv_bfloat16* __restrict__ hi, __nv_bfloat16* __restrict__ lo)
{
    long n4 = (long)ZZ * Ll * Ll / 4;
    for (long i = (long)blockIdx.x * blockDim.x + threadIdx.x; i < n4;
         i += (long)gridDim.x * blockDim.x) {
        long x = i * 4;
        long z = x >> 18;
        int r = (int)((x >> 9) & 511);
        int c = (int)(x & 511);
        float dr = dinv[z * Ll + r];
        const float* dc = dinv + z * Ll + c;
        float4 v = ((const float4*)A)[i];
        float f[4] = { v.x, v.y, v.z, v.w };
#pragma unroll
        for (int j = 0; j < 4; j++) {
            float a = f[j] + ((c + j) == r ? 1.0f : 0.0f);
            f[j] = a * dr * dc[j];
        }
        __nv_bfloat16 h[4], l[4];
#pragma unroll
        for (int j = 0; j < 4; j++) {
            h[j] = __float2bfloat16(f[j]);
            l[j] = __float2bfloat16(f[j] - __bfloat162float(h[j]));
        }
        ((__nv_bfloat162*)hi)[2 * i]     = __halves2bfloat162(h[0], h[1]);
        ((__nv_bfloat162*)hi)[2 * i + 1] = __halves2bfloat162(h[2], h[3]);
        ((__nv_bfloat162*)lo)[2 * i]     = __halves2bfloat162(l[0], l[1]);
        ((__nv_bfloat162*)lo)[2 * i + 1] = __halves2bfloat162(l[2], l[3]);
    }
}

// ===========================================================================
// Adjacency (fp32 SIMT, symmetric tile pairs) — exact R12 version.
// ===========================================================================
__global__ __launch_bounds__(256) void adj_kernel(const float* __restrict__ S,
                                                  float* __restrict__ A)
{
    int z = blockIdx.z;
    const float* Sh = S + (long)z * Ll * Ll;
    float* Ah = A + (long)z * Ll * Ll;

    int rem = blockIdx.x;
    int ti = 0;
    while (rem >= (8 - ti)) { rem -= (8 - ti); ti++; }
    int tk = ti + rem;
    int i0 = ti * 64, k0 = tk * 64;

    __shared__ float Si[32][68];
    __shared__ float Sk[32][68];

    int tid = threadIdx.x;
    int tx = tid & 15, ty = tid >> 4;
    const float THR = 0.1f * 64.0f;

    float acc[4][4] = {};

    for (int j0 = 0; j0 < Ll; j0 += 32) {
#pragma unroll
        for (int t = 0; t < 8; t++) {
            int li = tid + t * 256;
            int i = li >> 5, j = li & 31;
            Si[j][i] = Sh[(long)(i0 + i) * Ll + j0 + j];
            Sk[j][i] = Sh[(long)(k0 + i) * Ll + j0 + j];
        }
        __syncthreads();
#pragma unroll
        for (int j = 0; j < 32; j++) {
            float4 av = *(const float4*)&Si[j][ty * 4];
            float4 bv = *(const float4*)&Sk[j][tx * 4];
            float a[4] = {av.x, av.y, av.z, av.w};
            float b[4] = {bv.x, bv.y, bv.z, bv.w};
#pragma unroll
            for (int ii = 0; ii < 4; ii++)
#pragma unroll
                for (int kk = 0; kk < 4; kk++) {
                    float t = a[ii] * b[kk];
                    if (t > THR) acc[ii][kk] += t;
                }
        }
        __syncthreads();
    }

    const float inv = 1.0f / (64.0f * 512.0f);
#pragma unroll
    for (int ii = 0; ii < 4; ii++)
#pragma unroll
        for (int kk = 0; kk < 4; kk++) {
            int gi = i0 + ty * 4 + ii, gk = k0 + tx * 4 + kk;
            float v = (gi == gk) ? 0.0f : acc[ii][kk] * inv;
            Ah[(long)gi * Ll + gk] = v;
            if (ti != tk) Ah[(long)gk * Ll + gi] = v;
        }
}

__global__ __launch_bounds__(256) void rowsum_kernel(const float* __restrict__ A,
                                                     float* __restrict__ dinv)
{
    long row = blockIdx.x;
    const float* a = A + row * Ll;
    int t = threadIdx.x;
    float s = a[t] + a[t + 256];
#pragma unroll
    for (int o = 16; o > 0; o >>= 1) s += __shfl_xor_sync(0xFFFFFFFFu, s, o);
    __shared__ float red[8];
    if ((t & 31) == 0) red[t >> 5] = s;
    __syncthreads();
    if (t == 0) {
        float tot = 1.0f;
        for (int w = 0; w < 8; w++) tot += red[w];
        tot = fmaxf(tot, 1e-6f);
        dinv[row] = rsqrtf(tot);
    }
}

// softmax fused with bf16 hi/lo split of the attn weights
__global__ __launch_bounds__(256) void softmax_split(
    const float* __restrict__ S, __nv_bfloat16* __restrict__ hi,
    __nv_bfloat16* __restrict__ lo)
{
    long row = blockIdx.x;
    const float* s = S + row * Ll;
    int t = threadIdx.x;
    float v0 = s[t], v1 = s[t + 256];

    __shared__ float red[8];
    float m = fmaxf(v0, v1);
#pragma unroll
    for (int o = 16; o > 0; o >>= 1) m = fmaxf(m, __shfl_xor_sync(0xFFFFFFFFu, m, o));
    if ((t & 31) == 0) red[t >> 5] = m;
    __syncthreads();
    float mm = red[0];
#pragma unroll
    for (int w = 1; w < 8; w++) mm = fmaxf(mm, red[w]);
    __syncthreads();

    float e0 = expf(v0 - mm), e1 = expf(v1 - mm);
    float ssum = e0 + e1;
#pragma unroll
    for (int o = 16; o > 0; o >>= 1) ssum += __shfl_xor_sync(0xFFFFFFFFu, ssum, o);
    if ((t & 31) == 0) red[t >> 5] = ssum;
    __syncthreads();
    float tot = 0.0f;
#pragma unroll
    for (int w = 0; w < 8; w++) tot += red[w];
    float inv = 1.0f / tot;
    float p0 = e0 * inv, p1 = e1 * inv;
    __nv_bfloat16 h0 = __float2bfloat16(p0);
    __nv_bfloat16 h1 = __float2bfloat16(p1);
    hi[row * Ll + t]       = h0;
    hi[row * Ll + t + 256] = h1;
    lo[row * Ll + t]       = __float2bfloat16(p0 - __bfloat162float(h0));
    lo[row * Ll + t + 256] = __float2bfloat16(p1 - __bfloat162float(h1));
}

// ===========================================================================
extern "C" void kernel_launch(void* const* d_in, const int* in_sizes, int n_in,
                              void* d_out, int out_size)
{
    const float* x  = (const float*)d_in[0];
    const float* Wq = (const float*)d_in[1];
    const float* Wk = (const float*)d_in[2];
    const float* Wv = (const float*)d_in[3];
    const float* Wo = (const float*)d_in[4];
    float* out = (float*)d_out;

    float *Sp, *Ap, *Dp;
    cudaGetSymbolAddress((void**)&Sp, g_S);
    cudaGetSymbolAddress((void**)&Ap, g_A);
    cudaGetSymbolAddress((void**)&Dp, g_dinv);

    __nv_bfloat16 *xH, *xL, *WTH, *WTL, *QKH, *QKL, *VTH, *VTL;
    __nv_bfloat16 *AhH, *AhL, *STH, *STL, *TH, *TL;
    cudaGetSymbolAddress((void**)&xH, g_x_hi);
    cudaGetSymbolAddress((void**)&xL, g_x_lo);
    cudaGetSymbolAddress((void**)&WTH, g_WT_hi);
    cudaGetSymbolAddress((void**)&WTL, g_WT_lo);
    cudaGetSymbolAddress((void**)&QKH, g_QKV_hi);
    cudaGetSymbolAddress((void**)&QKL, g_QKV_lo);
    cudaGetSymbolAddress((void**)&VTH, g_VT_hi);
    cudaGetSymbolAddress((void**)&VTL, g_VT_lo);
    cudaGetSymbolAddress((void**)&AhH, g_Ah_hi);
    cudaGetSymbolAddress((void**)&AhL, g_Ah_lo);
    cudaGetSymbolAddress((void**)&STH, g_ST_hi);
    cudaGetSymbolAddress((void**)&STL, g_ST_lo);
    cudaGetSymbolAddress((void**)&TH, g_T_hi);
    cudaGetSymbolAddress((void**)&TL, g_T_lo);

    // dynamic smem sizes: AM=2: 81920B; AM=1: 61440B
    const int SM2 = 2 * (2 * 128 * PADR + 2 * 128 * PADR) * 2;
    const int SM1 = 2 * (2 * 128 * PADR + 2 * 64 * PADR) * 2;
    cudaFuncSetAttribute(tc_gemm_g<2>, cudaFuncAttributeMaxDynamicSharedMemorySize, SM2);
    cudaFuncSetAttribute(tc_gemm_g<1>, cudaFuncAttributeMaxDynamicSharedMemorySize, SM1);

    // Launch order: adj_kernel is the 4th launch (ncu captures launch #4).
    // 1) all input splits (x straight + 4 W transposes)
    combo_split<<<dim3(16, 16, 8), 256>>>(x, Wq, Wk, Wv, Wo, xH, xL, WTH, WTL);

    // 2) QKV = x @ [Wq|Wk|Wv] -> bf16 hi/lo [2048 x 1536]  (AM=1: grid 384)
    tc_gemm_g<1><<<dim3(24, 16, 1), 256, SM1>>>(
        xH, xL, Dd, 0, 0,
        WTH, WTL, Dd, 0, 0,
        QKH, QKL, nullptr, 3 * Dd, 0, 0,
        Dd, 1, 1.0f, 0);

    // 3) S = Q @ K^T per head -> fp32 g_S
    tc_gemm_g<2><<<dim3(4, 4, ZZ), 256, SM2>>>(
        QKH, QKL, 3 * Dd, (long)Ll * 3 * Dd, HDd,
        QKH + Dd, QKL + Dd, 3 * Dd, (long)Ll * 3 * Dd, HDd,
        nullptr, nullptr, Sp, Ll, (long)Hh * LL2, LL2,
        HDd, Hh, 1.0f, 1);

    // 4) adjacency  <- profiled launch
    adj_kernel<<<dim3(36, 1, ZZ), 256>>>(Sp, Ap);

    // 5) degrees
    rowsum_kernel<<<ZZ * Ll, 256>>>(Ap, Dp);

    // 6) fused A_hat + split
    ahat_split_kernel<<<4096, 256>>>(Ap, Dp, AhH, AhL);

    // 7) S^T split (B operand of jump1)
    split_trans_kernel<<<dim3(16, 16, ZZ), 256>>>(Sp, STH, STL);

    // 8) T = A_hat @ S -> bf16 hi/lo
    tc_gemm_g<2><<<dim3(4, 4, ZZ), 256, SM2>>>(
        AhH, AhL, Ll, LL2, 0,
        STH, STL, Ll, LL2, 0,
        TH, TL, nullptr, Ll, LL2, 0,
        Ll, 1, 1.0f, 0);

    // 9) S_jump = (T @ A_hat) / 8 -> fp32 g_S
    tc_gemm_g<2><<<dim3(4, 4, ZZ), 256, SM2>>>(
        TH, TL, Ll, LL2, 0,
        AhH, AhL, Ll, LL2, 0,
        nullptr, nullptr, Sp, Ll, LL2, 0,
        Ll, 1, 0.125f, 1);

    // 10) softmax + attn split (into ST buffers)
    softmax_split<<<ZZ * Ll, 256>>>(Sp, STH, STL);

    // 11) V^T extraction from QKV
    vt_transpose<<<dim3(16, 1, ZZ), 256>>>(QKH, QKL, VTH, VTL);

    // 12) O = attn @ V -> bf16 hi/lo into T buffers
    tc_gemm_g<1><<<dim3(1, 4, ZZ), 256, SM1>>>(
        STH, STL, Ll, (long)Hh * LL2, LL2,
        VTH, VTL, Ll, (long)Hh * HDd * Ll, (long)HDd * Ll,
        TH, TL, nullptr, Dd, (long)Ll * Dd, HDd,
        Ll, Hh, 1.0f, 0);

    // 13) out = O @ Wo -> fp32 d_out  (AM=1: grid 128)
    tc_gemm_g<1><<<dim3(8, 16, 1), 256, SM1>>>(
        TH, TL, Dd, 0, 0,
        WTH + 3L * 512 * 512, WTL + 3L * 512 * 512, Dd, 0, 0,
        nullptr, nullptr, out, Dd, 0, 0,
        Dd, 1, 1.0f, 1);
}